// round 2
// baseline (speedup 1.0000x reference)
#include <cuda_runtime.h>

#define N_NODES 100000
#define N_EDGES 1600000
#define D 128
#define SCAN_BLOCKS 98   // ceil(100000/1024)

typedef unsigned long long ull;

// ---------------- scratch (static __device__, no allocation) ----------------
__device__ float g_p[(size_t)N_NODES * D];   // X @ W_l   (to be aggregated)
__device__ float g_q[(size_t)N_NODES * D];   // X @ W_r   (root path)
__device__ float g_h[(size_t)N_NODES * D];   // layer-1 output
__device__ int   g_cnt[N_NODES];
__device__ int   g_offs[N_NODES + 1];
__device__ int   g_cursor[N_NODES];
__device__ int   g_bsums[SCAN_BLOCKS];
__device__ int   g_esrc[N_EDGES];
__device__ int   g_is64;

// ---------------- packed f32x2 helpers --------------------------------------
__device__ __forceinline__ ull splat2(float a) {
    ull r; unsigned u = __float_as_uint(a);
    asm("mov.b64 %0, {%1, %1};" : "=l"(r) : "r"(u));
    return r;
}
__device__ __forceinline__ void ffma2(ull& d, ull a, ull b) {
    asm("fma.rn.f32x2 %0, %1, %2, %3;" : "=l"(d) : "l"(a), "l"(b), "l"(d));
}
__device__ __forceinline__ float2 unpack2(ull v) {
    unsigned lo, hi;
    asm("mov.b64 {%0, %1}, %2;" : "=r"(lo), "=r"(hi) : "l"(v));
    return make_float2(__uint_as_float(lo), __uint_as_float(hi));
}

// ---------------- edge-index dtype detection ---------------------------------
// int64 values < 2^32 have zero high words at odd int32 positions; int32 data
// there is actual uniform indices (P[all 256 == 0] ~ 1e-1280).
__global__ void k_detect(const int* __restrict__ e) {
    __shared__ int nz;
    if (threadIdx.x == 0) nz = 0;
    __syncthreads();
    if (e[2 * threadIdx.x + 1] != 0) atomicAdd(&nz, 1);
    __syncthreads();
    if (threadIdx.x == 0) g_is64 = (nz == 0) ? 1 : 0;
}

__device__ __forceinline__ int load_idx(const int* __restrict__ e, long long pos, int is64) {
    return is64 ? e[2 * pos] : e[pos];
}

// ---------------- CSR build --------------------------------------------------
__global__ void k_zero_cnt() {
    int i = blockIdx.x * blockDim.x + threadIdx.x;
    if (i < N_NODES) g_cnt[i] = 0;
}

__global__ void k_hist(const int* __restrict__ e) {
    int i = blockIdx.x * blockDim.x + threadIdx.x;
    if (i < N_EDGES) {
        int d = load_idx(e, (long long)N_EDGES + i, g_is64);
        atomicAdd(&g_cnt[d], 1);
    }
}

__global__ void k_scan_blocks(int n) {
    __shared__ int s[1024];
    int i = blockIdx.x * 1024 + threadIdx.x;
    int v = (i < n) ? g_cnt[i] : 0;
    s[threadIdx.x] = v;
    __syncthreads();
    #pragma unroll
    for (int d = 1; d < 1024; d <<= 1) {
        int t = (threadIdx.x >= d) ? s[threadIdx.x - d] : 0;
        __syncthreads();
        s[threadIdx.x] += t;
        __syncthreads();
    }
    if (i < n) g_offs[i] = s[threadIdx.x] - v;      // exclusive within block
    if (threadIdx.x == 1023) g_bsums[blockIdx.x] = s[1023];
}

__global__ void k_scan_sums(int nb) {
    if (threadIdx.x == 0) {
        int run = 0;
        for (int b = 0; b < nb; b++) { int t = g_bsums[b]; g_bsums[b] = run; run += t; }
    }
}

__global__ void k_add_offs(int n, int e) {
    int i = blockIdx.x * 1024 + threadIdx.x;
    if (i < n) {
        int o = g_offs[i] + g_bsums[blockIdx.x];
        g_offs[i] = o;
        g_cursor[i] = o;
    }
    if (i == 0) g_offs[n] = e;
}

__global__ void k_fill(const int* __restrict__ e) {
    int i = blockIdx.x * blockDim.x + threadIdx.x;
    if (i >= N_EDGES) return;
    int is64 = g_is64;
    int d = load_idx(e, (long long)N_EDGES + i, is64);
    int s = load_idx(e, (long long)i, is64);
    int pos = atomicAdd(&g_cursor[d], 1);
    g_esrc[pos] = s;
}

// ---------------- GEMM: C[n,128] = X[n,128] @ W[128,128] --------------------
// 128-row tile, K chunked by 32 (32KB static smem), 256 threads, 8x8 micro-tile,
// packed fma.rn.f32x2 (FFMA2) for 2x fp32 rate.
__global__ void k_gemm(const float* __restrict__ Xe, int xsel,
                       const float* __restrict__ W, int csel, int n) {
    __shared__ float As[32 * 128];   // [k][m] transposed
    __shared__ float Bs[32 * 128];   // [k][nn]
    const float* __restrict__ X = xsel ? g_h : Xe;
    float* __restrict__ C = csel ? g_q : g_p;

    int tid = threadIdx.x;
    int row0 = blockIdx.x * 128;
    int tx = tid & 15, ty = tid >> 4;

    ull acc[8][4];
    #pragma unroll
    for (int m = 0; m < 8; m++)
        #pragma unroll
        for (int p = 0; p < 4; p++) acc[m][p] = 0ULL;

    int r = tid >> 1;
    int hb = (tid & 1) * 16;
    int gr = row0 + r;

    for (int kk = 0; kk < 128; kk += 32) {
        __syncthreads();
        // load W chunk [kk..kk+31][0..127], coalesced
        {
            const float4* Wv = (const float4*)(W + kk * 128);
            float4* Bv = (float4*)Bs;
            #pragma unroll
            for (int i = 0; i < 4; i++) Bv[tid + 256 * i] = Wv[tid + 256 * i];
        }
        // load X tile chunk, transpose into As[k][m]
        {
            const float* xr = X + (size_t)gr * 128 + kk + hb;
            #pragma unroll
            for (int i = 0; i < 4; i++) {
                float4 v = make_float4(0.f, 0.f, 0.f, 0.f);
                if (gr < n) v = *(const float4*)(xr + i * 4);
                int c = hb + i * 4;
                As[(c + 0) * 128 + r] = v.x;
                As[(c + 1) * 128 + r] = v.y;
                As[(c + 2) * 128 + r] = v.z;
                As[(c + 3) * 128 + r] = v.w;
            }
        }
        __syncthreads();

        const float* ap = As + ty * 8;
        const float* bp = Bs + tx * 8;
        #pragma unroll 8
        for (int k = 0; k < 32; k++) {
            float4 a0 = *(const float4*)(ap + k * 128);
            float4 a1 = *(const float4*)(ap + k * 128 + 4);
            double2 d0 = *(const double2*)(bp + k * 128);
            double2 d1 = *(const double2*)(bp + k * 128 + 4);
            ull b0 = __double_as_longlong(d0.x);
            ull b1 = __double_as_longlong(d0.y);
            ull b2 = __double_as_longlong(d1.x);
            ull b3 = __double_as_longlong(d1.y);
            float af[8] = {a0.x, a0.y, a0.z, a0.w, a1.x, a1.y, a1.z, a1.w};
            #pragma unroll
            for (int m = 0; m < 8; m++) {
                ull am = splat2(af[m]);
                ffma2(acc[m][0], am, b0);
                ffma2(acc[m][1], am, b1);
                ffma2(acc[m][2], am, b2);
                ffma2(acc[m][3], am, b3);
            }
        }
    }

    #pragma unroll
    for (int m = 0; m < 8; m++) {
        int row = row0 + ty * 8 + m;
        if (row < n) {
            float2 f0 = unpack2(acc[m][0]);
            float2 f1 = unpack2(acc[m][1]);
            float2 f2 = unpack2(acc[m][2]);
            float2 f3 = unpack2(acc[m][3]);
            float4* dst = (float4*)(C + (size_t)row * 128 + tx * 8);
            dst[0] = make_float4(f0.x, f0.y, f1.x, f1.y);
            dst[1] = make_float4(f2.x, f2.y, f3.x, f3.y);
        }
    }
}

// ---------------- aggregation: out = [relu]( mean_agg(g_p) + b + g_q ) ------
// one warp per destination node; lane l owns float4 (cols 4l..4l+3)
__global__ void k_agg(const float* __restrict__ bias, float* __restrict__ oext,
                      int osel, int do_relu) {
    int w = (blockIdx.x * blockDim.x + threadIdx.x) >> 5;
    if (w >= N_NODES) return;
    const float* __restrict__ P = g_p;
    const float* __restrict__ Q = g_q;
    float* __restrict__ out = osel ? oext : g_h;

    int lane = threadIdx.x & 31;
    int s0 = g_offs[w], s1 = g_offs[w + 1];

    float4 acc = make_float4(0.f, 0.f, 0.f, 0.f);
    int e = s0;
    for (; e + 4 <= s1; e += 4) {
        int i0 = g_esrc[e], i1 = g_esrc[e + 1], i2 = g_esrc[e + 2], i3 = g_esrc[e + 3];
        float4 v0 = ((const float4*)(P + (size_t)i0 * 128))[lane];
        float4 v1 = ((const float4*)(P + (size_t)i1 * 128))[lane];
        float4 v2 = ((const float4*)(P + (size_t)i2 * 128))[lane];
        float4 v3 = ((const float4*)(P + (size_t)i3 * 128))[lane];
        acc.x += (v0.x + v1.x) + (v2.x + v3.x);
        acc.y += (v0.y + v1.y) + (v2.y + v3.y);
        acc.z += (v0.z + v1.z) + (v2.z + v3.z);
        acc.w += (v0.w + v1.w) + (v2.w + v3.w);
    }
    for (; e < s1; e++) {
        int i0 = g_esrc[e];
        float4 v0 = ((const float4*)(P + (size_t)i0 * 128))[lane];
        acc.x += v0.x; acc.y += v0.y; acc.z += v0.z; acc.w += v0.w;
    }

    int deg = s1 - s0;
    float scale = 1.0f / (float)(deg > 0 ? deg : 1);
    float4 qv = ((const float4*)(Q + (size_t)w * 128))[lane];
    float4 bv = ((const float4*)bias)[lane];
    float4 r;
    r.x = fmaf(acc.x, scale, bv.x + qv.x);
    r.y = fmaf(acc.y, scale, bv.y + qv.y);
    r.z = fmaf(acc.z, scale, bv.z + qv.z);
    r.w = fmaf(acc.w, scale, bv.w + qv.w);
    if (do_relu) {
        r.x = fmaxf(r.x, 0.f); r.y = fmaxf(r.y, 0.f);
        r.z = fmaxf(r.z, 0.f); r.w = fmaxf(r.w, 0.f);
    }
    ((float4*)(out + (size_t)w * 128))[lane] = r;
}

// ---------------- launch -----------------------------------------------------
extern "C" void kernel_launch(void* const* d_in, const int* in_sizes, int n_in,
                              void* d_out, int out_size) {
    const float* x   = (const float*)d_in[0];
    const int*   ei  = (const int*)d_in[1];
    const float* W1l = (const float*)d_in[2];
    const float* b1  = (const float*)d_in[3];
    const float* W1r = (const float*)d_in[4];
    const float* W2l = (const float*)d_in[5];
    const float* b2  = (const float*)d_in[6];
    const float* W2r = (const float*)d_in[7];
    float* out = (float*)d_out;

    const int GEMM_GRID = (N_NODES + 127) / 128;      // 782
    const int EDGE_GRID = (N_EDGES + 255) / 256;
    const int AGG_GRID  = (N_NODES * 32 + 255) / 256;

    // ---- CSR build (dst-grouped pull lists) ----
    k_detect<<<1, 256>>>(ei);
    k_zero_cnt<<<(N_NODES + 255) / 256, 256>>>();
    k_hist<<<EDGE_GRID, 256>>>(ei);
    k_scan_blocks<<<SCAN_BLOCKS, 1024>>>(N_NODES);
    k_scan_sums<<<1, 32>>>(SCAN_BLOCKS);
    k_add_offs<<<SCAN_BLOCKS, 1024>>>(N_NODES, N_EDGES);
    k_fill<<<EDGE_GRID, 256>>>(ei);

    // ---- layer 1: transform-then-aggregate (aggregation is linear) ----
    k_gemm<<<GEMM_GRID, 256>>>(x, 0, W1l, 0, N_NODES);
    k_gemm<<<GEMM_GRID, 256>>>(x, 0, W1r, 1, N_NODES);
    k_agg<<<AGG_GRID, 256>>>(b1, out, 0, 1);

    // ---- layer 2 ----
    k_gemm<<<GEMM_GRID, 256>>>((const float*)0, 1, W2l, 0, N_NODES);
    k_gemm<<<GEMM_GRID, 256>>>((const float*)0, 1, W2r, 1, N_NODES);
    k_agg<<<AGG_GRID, 256>>>(b2, out, 1, 0);
}

// round 3
// speedup vs baseline: 1.5687x; 1.5687x over previous
#include <cuda_runtime.h>

#define N_NODES 100000
#define N_EDGES 1600000
#define D 128
#define SCAN_BLOCKS 98   // ceil(100000/1024)

// ---------------- scratch (static __device__, no allocation) ----------------
__device__ float g_p[(size_t)N_NODES * D];   // X @ W_l   (to be aggregated)
__device__ float g_q[(size_t)N_NODES * D];   // X @ W_r   (root path)
__device__ float g_h[(size_t)N_NODES * D];   // layer-1 output
__device__ int   g_cnt[N_NODES];
__device__ int   g_offs[N_NODES + 1];
__device__ int   g_cursor[N_NODES];
__device__ int   g_bsums[SCAN_BLOCKS];
__device__ int   g_esrc[N_EDGES];
__device__ int   g_is64;

// ---------------- tf32 helpers ----------------------------------------------
__device__ __forceinline__ unsigned tf32(float f) {
    unsigned u;
    asm("cvt.rna.tf32.f32 %0, %1;" : "=r"(u) : "f"(f));
    return u;
}
__device__ __forceinline__ void mma_tf32(float c[4], const unsigned a[4], const unsigned b[2]) {
    asm volatile(
        "mma.sync.aligned.m16n8k8.row.col.f32.tf32.tf32.f32 "
        "{%0,%1,%2,%3}, {%4,%5,%6,%7}, {%8,%9}, {%0,%1,%2,%3};\n"
        : "+f"(c[0]), "+f"(c[1]), "+f"(c[2]), "+f"(c[3])
        : "r"(a[0]), "r"(a[1]), "r"(a[2]), "r"(a[3]), "r"(b[0]), "r"(b[1]));
}

// ---------------- edge-index dtype detection ---------------------------------
// int64 values < 2^32 have zero high words at odd int32 positions; int32 data
// there is actual uniform indices (P[all 256 == 0] ~ 1e-1280).
__global__ void k_detect(const int* __restrict__ e) {
    __shared__ int nz;
    if (threadIdx.x == 0) nz = 0;
    __syncthreads();
    if (e[2 * threadIdx.x + 1] != 0) atomicAdd(&nz, 1);
    __syncthreads();
    if (threadIdx.x == 0) g_is64 = (nz == 0) ? 1 : 0;
}

__device__ __forceinline__ int load_idx(const int* __restrict__ e, long long pos, int is64) {
    return is64 ? e[2 * pos] : e[pos];
}

// ---------------- CSR build --------------------------------------------------
__global__ void k_zero_cnt() {
    int i = blockIdx.x * blockDim.x + threadIdx.x;
    if (i < N_NODES) g_cnt[i] = 0;
}

__global__ void k_hist(const int* __restrict__ e) {
    int i = blockIdx.x * blockDim.x + threadIdx.x;
    if (i < N_EDGES) {
        int d = load_idx(e, (long long)N_EDGES + i, g_is64);
        atomicAdd(&g_cnt[d], 1);
    }
}

__global__ void k_scan_blocks(int n) {
    __shared__ int s[1024];
    int i = blockIdx.x * 1024 + threadIdx.x;
    int v = (i < n) ? g_cnt[i] : 0;
    s[threadIdx.x] = v;
    __syncthreads();
    #pragma unroll
    for (int d = 1; d < 1024; d <<= 1) {
        int t = (threadIdx.x >= d) ? s[threadIdx.x - d] : 0;
        __syncthreads();
        s[threadIdx.x] += t;
        __syncthreads();
    }
    if (i < n) g_offs[i] = s[threadIdx.x] - v;      // exclusive within block
    if (threadIdx.x == 1023) g_bsums[blockIdx.x] = s[1023];
}

__global__ void k_scan_sums(int nb) {
    if (threadIdx.x == 0) {
        int run = 0;
        for (int b = 0; b < nb; b++) { int t = g_bsums[b]; g_bsums[b] = run; run += t; }
    }
}

__global__ void k_add_offs(int n, int e) {
    int i = blockIdx.x * 1024 + threadIdx.x;
    if (i < n) {
        int o = g_offs[i] + g_bsums[blockIdx.x];
        g_offs[i] = o;
        g_cursor[i] = o;
    }
    if (i == 0) g_offs[n] = e;
}

__global__ void k_fill(const int* __restrict__ e) {
    int i = blockIdx.x * blockDim.x + threadIdx.x;
    if (i >= N_EDGES) return;
    int is64 = g_is64;
    int d = load_idx(e, (long long)N_EDGES + i, is64);
    int s = load_idx(e, (long long)i, is64);
    int pos = atomicAdd(&g_cursor[d], 1);
    g_esrc[pos] = s;
}

// ---------------- fused dual GEMM: P = X@Wl, Q = X@Wr (tf32 MMA) ------------
// 128-row tile per block. 512 threads = 16 warps:
//   warps 0-7  -> P (mat 0), warps 8-15 -> Q (mat 1)
//   within a mat: 4x2 grid of 32x64 warp tiles (m16n8k8 frags: 2 m x 8 n)
__global__ __launch_bounds__(512) void k_gemm2(const float* __restrict__ Xe, int xsel,
                                               const float* __restrict__ Wl,
                                               const float* __restrict__ Wr, int n) {
    __shared__ unsigned As[128][20];       // [row][k] stride 20 (16 data + pad)
    __shared__ unsigned Bs[2][16][136];    // [mat][k][col] stride 136
    const float* __restrict__ X = xsel ? g_h : Xe;

    int tid = threadIdx.x;
    int wid = tid >> 5, lane = tid & 31;
    int mat = wid >> 3;             // 0 = P, 1 = Q
    int wm = (wid & 7) >> 1;        // 0..3  (row tile)
    int wn = wid & 1;               // 0..1  (col tile)
    int gid = lane >> 2, tig = lane & 3;
    int row0 = blockIdx.x * 128;

    float c[2][8][4];
    #pragma unroll
    for (int mi = 0; mi < 2; mi++)
        #pragma unroll
        for (int ni = 0; ni < 8; ni++)
            #pragma unroll
            for (int j = 0; j < 4; j++) c[mi][ni][j] = 0.f;

    // loader indices
    int arow = tid >> 2;            // 0..127
    int acol = (tid & 3) * 4;       // 0,4,8,12
    int brow = tid >> 5;            // 0..15
    int bcol = (tid & 31) * 4;      // 0..124

    const float* xr = X + (size_t)(row0 + arow) * 128 + acol;
    bool aval = (row0 + arow) < n;

    for (int kk = 0; kk < 128; kk += 16) {
        __syncthreads();
        // A chunk: 128 x 16, converted to tf32
        {
            float4 v = make_float4(0.f, 0.f, 0.f, 0.f);
            if (aval) v = *(const float4*)(xr + kk);
            As[arow][acol + 0] = tf32(v.x);
            As[arow][acol + 1] = tf32(v.y);
            As[arow][acol + 2] = tf32(v.z);
            As[arow][acol + 3] = tf32(v.w);
        }
        // B chunks: 16 x 128 each weight
        {
            float4 vl = *(const float4*)(Wl + (size_t)(kk + brow) * 128 + bcol);
            float4 vr = *(const float4*)(Wr + (size_t)(kk + brow) * 128 + bcol);
            Bs[0][brow][bcol + 0] = tf32(vl.x);
            Bs[0][brow][bcol + 1] = tf32(vl.y);
            Bs[0][brow][bcol + 2] = tf32(vl.z);
            Bs[0][brow][bcol + 3] = tf32(vl.w);
            Bs[1][brow][bcol + 0] = tf32(vr.x);
            Bs[1][brow][bcol + 1] = tf32(vr.y);
            Bs[1][brow][bcol + 2] = tf32(vr.z);
            Bs[1][brow][bcol + 3] = tf32(vr.w);
        }
        __syncthreads();

        #pragma unroll
        for (int ks = 0; ks < 2; ks++) {
            unsigned a[2][4], b[8][2];
            #pragma unroll
            for (int mi = 0; mi < 2; mi++) {
                int r = wm * 32 + mi * 16 + gid;
                a[mi][0] = As[r][ks * 8 + tig];
                a[mi][1] = As[r + 8][ks * 8 + tig];
                a[mi][2] = As[r][ks * 8 + tig + 4];
                a[mi][3] = As[r + 8][ks * 8 + tig + 4];
            }
            #pragma unroll
            for (int ni = 0; ni < 8; ni++) {
                int col = wn * 64 + ni * 8 + gid;
                b[ni][0] = Bs[mat][ks * 8 + tig][col];
                b[ni][1] = Bs[mat][ks * 8 + tig + 4][col];
            }
            #pragma unroll
            for (int mi = 0; mi < 2; mi++)
                #pragma unroll
                for (int ni = 0; ni < 8; ni++)
                    mma_tf32(c[mi][ni], a[mi], b[ni]);
        }
    }

    // epilogue
    float* __restrict__ C = mat ? g_q : g_p;
    #pragma unroll
    for (int mi = 0; mi < 2; mi++) {
        int r = row0 + wm * 32 + mi * 16 + gid;
        #pragma unroll
        for (int ni = 0; ni < 8; ni++) {
            int cl = wn * 64 + ni * 8 + tig * 2;
            if (r < n)
                *(float2*)(C + (size_t)r * 128 + cl) = make_float2(c[mi][ni][0], c[mi][ni][1]);
            if (r + 8 < n)
                *(float2*)(C + (size_t)(r + 8) * 128 + cl) = make_float2(c[mi][ni][2], c[mi][ni][3]);
        }
    }
}

// ---------------- aggregation: out = [relu]( mean_agg(g_p) + b + g_q ) ------
// one warp per destination node; lane l owns float4 (cols 4l..4l+3)
__global__ void k_agg(const float* __restrict__ bias, float* __restrict__ oext,
                      int osel, int do_relu) {
    int w = (blockIdx.x * blockDim.x + threadIdx.x) >> 5;
    if (w >= N_NODES) return;
    const float* __restrict__ P = g_p;
    const float* __restrict__ Q = g_q;
    float* __restrict__ out = osel ? oext : g_h;

    int lane = threadIdx.x & 31;
    int s0 = g_offs[w], s1 = g_offs[w + 1];

    float4 acc = make_float4(0.f, 0.f, 0.f, 0.f);
    int e = s0;
    for (; e + 4 <= s1; e += 4) {
        int i0 = g_esrc[e], i1 = g_esrc[e + 1], i2 = g_esrc[e + 2], i3 = g_esrc[e + 3];
        float4 v0 = ((const float4*)(P + (size_t)i0 * 128))[lane];
        float4 v1 = ((const float4*)(P + (size_t)i1 * 128))[lane];
        float4 v2 = ((const float4*)(P + (size_t)i2 * 128))[lane];
        float4 v3 = ((const float4*)(P + (size_t)i3 * 128))[lane];
        acc.x += (v0.x + v1.x) + (v2.x + v3.x);
        acc.y += (v0.y + v1.y) + (v2.y + v3.y);
        acc.z += (v0.z + v1.z) + (v2.z + v3.z);
        acc.w += (v0.w + v1.w) + (v2.w + v3.w);
    }
    for (; e < s1; e++) {
        int i0 = g_esrc[e];
        float4 v0 = ((const float4*)(P + (size_t)i0 * 128))[lane];
        acc.x += v0.x; acc.y += v0.y; acc.z += v0.z; acc.w += v0.w;
    }

    int deg = s1 - s0;
    float scale = 1.0f / (float)(deg > 0 ? deg : 1);
    float4 qv = ((const float4*)(Q + (size_t)w * 128))[lane];
    float4 bv = ((const float4*)bias)[lane];
    float4 r;
    r.x = fmaf(acc.x, scale, bv.x + qv.x);
    r.y = fmaf(acc.y, scale, bv.y + qv.y);
    r.z = fmaf(acc.z, scale, bv.z + qv.z);
    r.w = fmaf(acc.w, scale, bv.w + qv.w);
    if (do_relu) {
        r.x = fmaxf(r.x, 0.f); r.y = fmaxf(r.y, 0.f);
        r.z = fmaxf(r.z, 0.f); r.w = fmaxf(r.w, 0.f);
    }
    ((float4*)(out + (size_t)w * 128))[lane] = r;
}

// ---------------- launch -----------------------------------------------------
extern "C" void kernel_launch(void* const* d_in, const int* in_sizes, int n_in,
                              void* d_out, int out_size) {
    const float* x   = (const float*)d_in[0];
    const int*   ei  = (const int*)d_in[1];
    const float* W1l = (const float*)d_in[2];
    const float* b1  = (const float*)d_in[3];
    const float* W1r = (const float*)d_in[4];
    const float* W2l = (const float*)d_in[5];
    const float* b2  = (const float*)d_in[6];
    const float* W2r = (const float*)d_in[7];
    float* out = (float*)d_out;

    const int GEMM_GRID = (N_NODES + 127) / 128;      // 782
    const int EDGE_GRID = (N_EDGES + 255) / 256;
    const int AGG_GRID  = (N_NODES * 32 + 255) / 256;

    // ---- CSR build (dst-grouped pull lists) ----
    k_detect<<<1, 256>>>(ei);
    k_zero_cnt<<<(N_NODES + 255) / 256, 256>>>();
    k_hist<<<EDGE_GRID, 256>>>(ei);
    k_scan_blocks<<<SCAN_BLOCKS, 1024>>>(N_NODES);
    k_scan_sums<<<1, 32>>>(SCAN_BLOCKS);
    k_add_offs<<<SCAN_BLOCKS, 1024>>>(N_NODES, N_EDGES);
    k_fill<<<EDGE_GRID, 256>>>(ei);

    // ---- layer 1: transform-then-aggregate (aggregation is linear) ----
    k_gemm2<<<GEMM_GRID, 512>>>(x, 0, W1l, W1r, N_NODES);
    k_agg<<<AGG_GRID, 256>>>(b1, out, 0, 1);

    // ---- layer 2 ----
    k_gemm2<<<GEMM_GRID, 512>>>((const float*)0, 1, W2l, W2r, N_NODES);
    k_agg<<<AGG_GRID, 256>>>(b2, out, 1, 0);
}